// round 8
// baseline (speedup 1.0000x reference)
#include <cuda_runtime.h>
#include <cuda_bf16.h>
#include <math.h>

#define D 128
#define QVS 256                   // qv row stride (a at 0..127, v at 128..255)
#define MAXN 50000
#define MAXE 600000

// ---------------- scratch (static device globals; no allocation) ----------------
__device__ float          g_yu[MAXN * D];
__device__ float          g_yi[MAXN * D];
__device__ __nv_bfloat16  g_agg[2][MAXN * D];        // 0: items (ui pass), 1: users (iu pass)
__device__ __nv_bfloat16  g_xbu[MAXN * D];
__device__ __nv_bfloat16  g_xbi[MAXN * D];
__device__ __nv_bfloat16  g_qv[2][MAXN * QVS];       // interleaved a|v per pass
__device__ float          g_A[4][D * D];             // A = qw^T @ W (fp32), per (layer,pass)
__device__ float          g_cbv[4][D];               // cb = qb @ W
__device__ __nv_bfloat16  g_Wmb[4][D * D];           // B^T in GEMM convention (bf16)
__device__ __nv_bfloat16  g_Vbb[4][D * D];           // v weights bf16
__device__ float          g_u[4][D];                 // u = A @ kb
__device__ float          g_w[4][D];                 // w = cb @ kw  (a-GEMM bias)
__device__ float          g_c0[4];                   // c0 = cb . kb
__device__ float          g_sum[4];
__device__ float          g_s[2][MAXN];              // per-src scalar s = x.u + c0 (per pass)
__device__ int            g_deg[2][MAXN];
__device__ int            g_cur[2][MAXN];
__device__ int            g_off_ui[MAXN + 1];
__device__ int            g_off_iu[MAXN + 1];
__device__ int            g_src_ui[MAXE];
__device__ int            g_src_iu[MAXE];

// ---------------- prep stage 1: A[p] = qw^T @ W, cb[p] = qb @ W (fp32) ----------------
struct Prep1 {
    const float* qw[4]; const float* qb[4]; const float* W[4];
    float* A; float* cb; float* psum;
};

__global__ void prep1_k(Prep1 pr)
{
    const int p  = blockIdx.y;
    const int bx = blockIdx.x;
    if (bx == 0 && threadIdx.x == 0) pr.psum[p] = 0.f;
    int id = bx * 256 + threadIdx.x;
    const float* qw = pr.qw[p];
    const float* W  = pr.W[p];
    if (id < D * D) {
        int d = id / D, j2 = id % D;
        float s = 0.f;
        #pragma unroll 8
        for (int j = 0; j < D; ++j) s = fmaf(qw[j * D + d], W[j * D + j2], s);
        pr.A[p * D * D + d * D + j2] = s;
    } else if (id < D * D + D) {
        int j2 = id - D * D;
        const float* qb = pr.qb[p];
        float s = 0.f;
        #pragma unroll 8
        for (int j = 0; j < D; ++j) s = fmaf(qb[j], W[j * D + j2], s);
        pr.cb[p * D + j2] = s;
    }
}

// ---------------- prep stage 2: B=A@kw -> Wmb (B^T bf16); Vbb; u,w,c0 ----------------
struct Prep2 {
    const float* kw[4]; const float* kb[4]; const float* vw[4];
    const float* A; const float* cb;
    __nv_bfloat16* Wmb; __nv_bfloat16* Vbb;
    float* u; float* w; float* c0;
};

__global__ void prep2_k(Prep2 pr)
{
    const int p  = blockIdx.y;
    const int bx = blockIdx.x;
    const float* A  = pr.A + p * D * D;
    const float* kw = pr.kw[p];
    if (bx < 64) {
        int o = bx * 256 + threadIdx.x;       // o = r*D + c : Wmb[r][c] = B[c][r]
        int r = o / D, c = o % D;
        float s = 0.f;
        #pragma unroll 8
        for (int j = 0; j < D; ++j) s = fmaf(A[c * D + j], kw[j * D + r], s);
        pr.Wmb[p * D * D + o] = __float2bfloat16(s);
    } else if (bx < 128) {
        int id = (bx - 64) * 256 + threadIdx.x;
        pr.Vbb[p * D * D + id] = __float2bfloat16(pr.vw[p][id]);
    } else {
        const float* kb = pr.kb[p];
        const float* cb = pr.cb + p * D;
        int t = threadIdx.x;
        if (t < D) {
            float s = 0.f;
            #pragma unroll 8
            for (int j = 0; j < D; ++j) s = fmaf(A[t * D + j], kb[j], s);
            pr.u[p * D + t] = s;
        } else if (t < 2 * D) {
            int r = t - D;
            float s = 0.f;
            #pragma unroll 8
            for (int j = 0; j < D; ++j) s = fmaf(cb[j], kw[j * D + r], s);
            pr.w[p * D + r] = s;
        } else if (t == 2 * D) {
            float s = 0.f;
            for (int j = 0; j < D; ++j) s = fmaf(cb[j], kb[j], s);
            pr.c0[p] = s;
        }
    }
}

// ---------------- conv: warp-per-row fp32->bf16 + s = x.u + c0 ----------------
struct ConvB {
    const float* x[2]; __nv_bfloat16* y[2];
    const float* u[2]; const float* c0[2]; float* s[2];
    int n[2];
};

__global__ __launch_bounds__(256) void conv_b16(ConvB cv)
{
    const int t    = blockIdx.y;
    const int lane = threadIdx.x & 31;
    const int warp = (blockIdx.x * 256 + threadIdx.x) >> 5;
    const int nw   = (gridDim.x * 256) >> 5;
    const int n    = cv.n[t];
    const float* __restrict__ x = cv.x[t];
    __nv_bfloat16* __restrict__ y = cv.y[t];
    const float4 uv = ((const float4*)cv.u[t])[lane];
    const float c0 = *cv.c0[t];
    float* __restrict__ s = cv.s[t];
    for (int node = warp; node < n; node += nw) {
        float4 v = ((const float4*)x)[node * 32 + lane];
        __nv_bfloat162 lo = __floats2bfloat162_rn(v.x, v.y);
        __nv_bfloat162 hi = __floats2bfloat162_rn(v.z, v.w);
        uint2 o;
        o.x = *(unsigned int*)&lo;
        o.y = *(unsigned int*)&hi;
        ((uint2*)y)[node * 32 + lane] = o;
        float p = v.x * uv.x + v.y * uv.y + v.z * uv.z + v.w * uv.w;
        #pragma unroll
        for (int of = 16; of; of >>= 1) p += __shfl_xor_sync(0xffffffffu, p, of);
        if (lane == 0) s[node] = p + c0;
    }
}

// ---------------- bf16 tensor-core batched GEMM: C[N,128] = bf16(X @ Wm^T + bias) ----------------
__device__ __forceinline__ void mma16816(float c[4],
                                         unsigned a0, unsigned a1, unsigned a2, unsigned a3,
                                         unsigned b0, unsigned b1)
{
    asm volatile("mma.sync.aligned.m16n8k16.row.col.f32.bf16.bf16.f32 "
                 "{%0,%1,%2,%3}, {%4,%5,%6,%7}, {%8,%9}, {%0,%1,%2,%3};"
                 : "+f"(c[0]), "+f"(c[1]), "+f"(c[2]), "+f"(c[3])
                 : "r"(a0), "r"(a1), "r"(a2), "r"(a3), "r"(b0), "r"(b1));
}

#define GSTRIDE 136   // smem row stride in bf16 elems; 68 words, 68 mod 32 = 4 -> conflict-free

struct GemmBatch {
    const __nv_bfloat16* X[4];
    const __nv_bfloat16* W[4];
    const float*         bias[4];
    __nv_bfloat16*       C[4];
    int                  N[4];
};

__global__ __launch_bounds__(256, 2) void gemm_batch(GemmBatch gb)
{
    extern __shared__ __nv_bfloat16 sh[];
    __nv_bfloat16* Xs = sh;                   // [128][GSTRIDE]
    __nv_bfloat16* Ws = sh + 128 * GSTRIDE;   // [128][GSTRIDE]
    const int g = blockIdx.y;
    const int N = gb.N[g];
    const int row0 = blockIdx.x * 128;
    if (row0 >= N) return;
    const __nv_bfloat16* __restrict__ X  = gb.X[g];
    const __nv_bfloat16* __restrict__ Wm = gb.W[g];
    const float* __restrict__ bias       = gb.bias[g];
    __nv_bfloat16* __restrict__ C        = gb.C[g];

    const int tid  = threadIdx.x;
    const int warp = tid >> 5, lane = tid & 31;

    #pragma unroll
    for (int i = 0; i < 8; ++i) {
        int seg = tid + i * 256;
        int r = seg >> 4, c = (seg & 15) << 3;
        *(uint4*)(Ws + r * GSTRIDE + c) = *(const uint4*)(Wm + r * D + c);
    }
    #pragma unroll
    for (int i = 0; i < 8; ++i) {
        int seg = tid + i * 256;
        int r = seg >> 4, c = (seg & 15) << 3;
        int gr = row0 + r;
        uint4 val = make_uint4(0u, 0u, 0u, 0u);
        if (gr < N) val = *(const uint4*)(X + (size_t)gr * D + c);
        *(uint4*)(Xs + r * GSTRIDE + c) = val;
    }
    __syncthreads();

    const int wm = warp & 3;
    const int wn = warp >> 2;
    const int qr = lane >> 2;
    const int kq = (lane & 3) * 2;

    float acc[2][8][4];
    #pragma unroll
    for (int m = 0; m < 2; ++m)
        #pragma unroll
        for (int nt = 0; nt < 8; ++nt)
            #pragma unroll
            for (int j = 0; j < 4; ++j) acc[m][nt][j] = 0.f;

    #pragma unroll
    for (int k0 = 0; k0 < D; k0 += 16) {
        unsigned a[2][4];
        #pragma unroll
        for (int m = 0; m < 2; ++m) {
            const __nv_bfloat16* base = Xs + (32 * wm + 16 * m + qr) * GSTRIDE + k0 + kq;
            a[m][0] = *(const unsigned*)(base);
            a[m][1] = *(const unsigned*)(base + 8 * GSTRIDE);
            a[m][2] = *(const unsigned*)(base + 8);
            a[m][3] = *(const unsigned*)(base + 8 * GSTRIDE + 8);
        }
        #pragma unroll
        for (int nt = 0; nt < 8; ++nt) {
            const __nv_bfloat16* bb = Ws + (64 * wn + nt * 8 + qr) * GSTRIDE + k0 + kq;
            unsigned b0 = *(const unsigned*)(bb);
            unsigned b1 = *(const unsigned*)(bb + 8);
            mma16816(acc[0][nt], a[0][0], a[0][1], a[0][2], a[0][3], b0, b1);
            mma16816(acc[1][nt], a[1][0], a[1][1], a[1][2], a[1][3], b0, b1);
        }
    }

    #pragma unroll
    for (int m = 0; m < 2; ++m) {
        int gr0 = row0 + 32 * wm + 16 * m + qr;
        int gr1 = gr0 + 8;
        #pragma unroll
        for (int nt = 0; nt < 8; ++nt) {
            int gc = 64 * wn + nt * 8 + kq;
            float b0f = bias[gc], b1f = bias[gc + 1];
            if (gr0 < N) {
                __nv_bfloat162 o = __floats2bfloat162_rn(acc[m][nt][0] + b0f, acc[m][nt][1] + b1f);
                *(__nv_bfloat162*)(C + (size_t)gr0 * QVS + gc) = o;
            }
            if (gr1 < N) {
                __nv_bfloat162 o = __floats2bfloat162_rn(acc[m][nt][2] + b0f, acc[m][nt][3] + b1f);
                *(__nv_bfloat162*)(C + (size_t)gr1 * QVS + gc) = o;
            }
        }
    }
}

// ---------------- CSR build (batched over both edge types) ----------------
struct CountB { const int* dst[2]; int* deg[2]; int E[2]; };

__global__ void count_b(CountB cb)
{
    const int t = blockIdx.y;
    const int* __restrict__ dst = cb.dst[t];
    int* __restrict__ deg = cb.deg[t];
    const int E = cb.E[t];
    for (int e = blockIdx.x * blockDim.x + threadIdx.x; e < E; e += gridDim.x * blockDim.x)
        atomicAdd(&deg[dst[e]], 1);
}

struct ScanB { const int* deg[2]; int* off[2]; int* cur[2]; int n[2]; };

__global__ __launch_bounds__(1024) void scan_b(ScanB sb)
{
    __shared__ int sh[1024];
    const int b = blockIdx.x;
    const int* __restrict__ deg = sb.deg[b];
    int* __restrict__ off = sb.off[b];
    int* __restrict__ cur = sb.cur[b];
    const int n = sb.n[b];
    int t = threadIdx.x;
    int c = (n + 1023) >> 10;
    int lo = t * c;
    int hi = lo + c; if (hi > n) hi = n;
    int s = 0;
    for (int i = lo; i < hi; ++i) s += deg[i];
    sh[t] = s;
    __syncthreads();
    for (int o = 1; o < 1024; o <<= 1) {
        int v = (t >= o) ? sh[t - o] : 0;
        __syncthreads();
        sh[t] += v;
        __syncthreads();
    }
    int base = sh[t] - s;
    for (int i = lo; i < hi; ++i) { off[i] = base; cur[i] = base; base += deg[i]; }
    if (t == 1023) off[n] = sh[1023];
}

struct FillB { const int* dst[2]; const int* src[2]; int* cur[2]; int* csrc[2]; int E[2]; };

__global__ void fill_b(FillB fb)
{
    const int t = blockIdx.y;
    const int* __restrict__ dst = fb.dst[t];
    const int* __restrict__ src = fb.src[t];
    int* __restrict__ cur = fb.cur[t];
    int* __restrict__ csrc = fb.csrc[t];
    const int E = fb.E[t];
    for (int e = blockIdx.x * blockDim.x + threadIdx.x; e < E; e += gridDim.x * blockDim.x) {
        int p = atomicAdd(&cur[dst[e]], 1);
        csrc[p] = src[e];
    }
}

// ------------- batched fused edge pass: score=(a_s.x_d + s_s)/sqrt(D), agg over exp ----------------
struct EdgeBatch {
    const __nv_bfloat16* qv[2];
    const __nv_bfloat16* xd[2];
    const float* sarr[2];
    const int* off[2];
    const int* csrc[2];
    __nv_bfloat16* agg[2];
    float* psum;                 // [2]
    int n[2];
};

__device__ __forceinline__ float edot(uint2 qr, float2 kl, float2 kh)
{
    float2 q0 = __bfloat1622float2(*(__nv_bfloat162*)&qr.x);
    float2 q1 = __bfloat1622float2(*(__nv_bfloat162*)&qr.y);
    return q0.x * kl.x + q0.y * kl.y + q1.x * kh.x + q1.y * kh.y;
}

__device__ __forceinline__ void eacc(float ex, uint2 vr,
                                     float& a0, float& a1, float& a2, float& a3)
{
    float2 v0 = __bfloat1622float2(*(__nv_bfloat162*)&vr.x);
    float2 v1 = __bfloat1622float2(*(__nv_bfloat162*)&vr.y);
    a0 = fmaf(ex, v0.x, a0);
    a1 = fmaf(ex, v0.y, a1);
    a2 = fmaf(ex, v1.x, a2);
    a3 = fmaf(ex, v1.y, a3);
}

__device__ __forceinline__ float lrexp(float t)
{
    float sc = t * 0.08838834764831845f;     // 1/sqrt(128)
    sc = sc > 0.f ? sc : 0.01f * sc;         // leaky_relu
    return __expf(sc);
}

__global__ __launch_bounds__(256) void fused_edge_batch(EdgeBatch eb)
{
    const int p    = blockIdx.y;
    const int lane = threadIdx.x & 31;
    const int warp = (blockIdx.x * 256 + threadIdx.x) >> 5;
    const int nw   = (gridDim.x * 256) >> 5;
    const __nv_bfloat16* __restrict__ qv = eb.qv[p];
    const __nv_bfloat16* __restrict__ xd = eb.xd[p];
    const float* __restrict__ sarr = eb.sarr[p];
    const int* __restrict__ off  = eb.off[p];
    const int* __restrict__ csrc = eb.csrc[p];
    __nv_bfloat16* __restrict__ agg = eb.agg[p];
    const int n = eb.n[p];
    const int lo4 = lane * 4;

    float S = 0.f;
    for (int node = warp; node < n; node += nw) {
        uint2 kr = *(const uint2*)(xd + (size_t)node * D + lo4);
        float2 kl = __bfloat1622float2(*(__nv_bfloat162*)&kr.x);
        float2 kh = __bfloat1622float2(*(__nv_bfloat162*)&kr.y);
        float a0 = 0.f, a1 = 0.f, a2 = 0.f, a3 = 0.f;
        const int beg = off[node], end = off[node + 1];
        int idx = beg;
        for (; idx + 4 <= end; idx += 4) {
            int c0 = csrc[idx + 0], c1 = csrc[idx + 1];
            int c2 = csrc[idx + 2], c3 = csrc[idx + 3];
            const __nv_bfloat16* b0 = qv + (size_t)c0 * QVS + lo4;
            const __nv_bfloat16* b1 = qv + (size_t)c1 * QVS + lo4;
            const __nv_bfloat16* b2 = qv + (size_t)c2 * QVS + lo4;
            const __nv_bfloat16* b3 = qv + (size_t)c3 * QVS + lo4;
            uint2 q0 = *(const uint2*)(b0);
            uint2 q1 = *(const uint2*)(b1);
            uint2 q2 = *(const uint2*)(b2);
            uint2 q3 = *(const uint2*)(b3);
            uint2 v0 = *(const uint2*)(b0 + 128);
            uint2 v1 = *(const uint2*)(b1 + 128);
            uint2 v2 = *(const uint2*)(b2 + 128);
            uint2 v3 = *(const uint2*)(b3 + 128);
            float s0 = sarr[c0], s1 = sarr[c1], s2 = sarr[c2], s3 = sarr[c3];
            float p0 = edot(q0, kl, kh);
            float p1 = edot(q1, kl, kh);
            float p2 = edot(q2, kl, kh);
            float p3 = edot(q3, kl, kh);
            #pragma unroll
            for (int o = 16; o; o >>= 1) {
                p0 += __shfl_xor_sync(0xffffffffu, p0, o);
                p1 += __shfl_xor_sync(0xffffffffu, p1, o);
                p2 += __shfl_xor_sync(0xffffffffu, p2, o);
                p3 += __shfl_xor_sync(0xffffffffu, p3, o);
            }
            float e0 = lrexp(p0 + s0);
            float e1 = lrexp(p1 + s1);
            float e2 = lrexp(p2 + s2);
            float e3 = lrexp(p3 + s3);
            eacc(e0, v0, a0, a1, a2, a3);
            eacc(e1, v1, a0, a1, a2, a3);
            eacc(e2, v2, a0, a1, a2, a3);
            eacc(e3, v3, a0, a1, a2, a3);
            S += (e0 + e1) + (e2 + e3);
        }
        for (; idx < end; ++idx) {
            int c0 = csrc[idx];
            const __nv_bfloat16* b0 = qv + (size_t)c0 * QVS + lo4;
            uint2 q0 = *(const uint2*)(b0);
            uint2 v0 = *(const uint2*)(b0 + 128);
            float s0 = sarr[c0];
            float p0 = edot(q0, kl, kh);
            #pragma unroll
            for (int o = 16; o; o >>= 1) p0 += __shfl_xor_sync(0xffffffffu, p0, o);
            float e0 = lrexp(p0 + s0);
            eacc(e0, v0, a0, a1, a2, a3);
            S += e0;
        }
        __nv_bfloat162 lo = __floats2bfloat162_rn(a0, a1);
        __nv_bfloat162 hi = __floats2bfloat162_rn(a2, a3);
        uint2 ob;
        ob.x = *(unsigned int*)&lo;
        ob.y = *(unsigned int*)&hi;
        *(uint2*)(agg + (size_t)node * D + lo4) = ob;
    }
    if (lane == 0 && S != 0.f) atomicAdd(&eb.psum[p], S);
}

// ---- warp-per-row: out = x + agg/S; optional bf16 emit; optional next-layer s = out.u + c0 ----
struct AxpyBatch {
    const float* xin[2];
    const __nv_bfloat16* agg[2];
    const float* gsum[2];
    float* out[2];
    __nv_bfloat16* outb[2];
    const float* u[2];           // null if no s needed
    const float* c0[2];
    float* sout[2];
    int n[2];
};

__global__ __launch_bounds__(256) void axpy_batch(AxpyBatch ab)
{
    const int t    = blockIdx.y;
    const int lane = threadIdx.x & 31;
    const int warp = (blockIdx.x * 256 + threadIdx.x) >> 5;
    const int nw   = (gridDim.x * 256) >> 5;
    const int n    = ab.n[t];
    const float inv = 1.0f / *ab.gsum[t];
    const float* __restrict__ xin = ab.xin[t];
    const __nv_bfloat16* __restrict__ agg = ab.agg[t];
    float* __restrict__ out = ab.out[t];
    __nv_bfloat16* __restrict__ outb = ab.outb[t];
    const bool do_s = (ab.u[t] != nullptr);
    float4 uv = make_float4(0.f, 0.f, 0.f, 0.f);
    float c0 = 0.f;
    if (do_s) { uv = ((const float4*)ab.u[t])[lane]; c0 = *ab.c0[t]; }

    for (int node = warp; node < n; node += nw) {
        int i = node * 32 + lane;
        float4 x = ((const float4*)xin)[i];
        uint2 ag = ((const uint2*)agg)[i];
        float2 al = __bfloat1622float2(*(__nv_bfloat162*)&ag.x);
        float2 ah = __bfloat1622float2(*(__nv_bfloat162*)&ag.y);
        float4 o;
        o.x = fmaf(inv, al.x, x.x);
        o.y = fmaf(inv, al.y, x.y);
        o.z = fmaf(inv, ah.x, x.z);
        o.w = fmaf(inv, ah.y, x.w);
        ((float4*)out)[i] = o;
        if (outb) {
            __nv_bfloat162 lo = __floats2bfloat162_rn(o.x, o.y);
            __nv_bfloat162 hi = __floats2bfloat162_rn(o.z, o.w);
            uint2 ob;
            ob.x = *(unsigned int*)&lo;
            ob.y = *(unsigned int*)&hi;
            ((uint2*)outb)[i] = ob;
        }
        if (do_s) {
            float p = o.x * uv.x + o.y * uv.y + o.z * uv.z + o.w * uv.w;
            #pragma unroll
            for (int of = 16; of; of >>= 1) p += __shfl_xor_sync(0xffffffffu, p, of);
            if (lane == 0) ab.sout[t][node] = p + c0;
        }
    }
}

// ---------------- host-side orchestration ----------------
#define GEMM_SMEM (2 * 128 * GSTRIDE * (int)sizeof(__nv_bfloat16))

extern "C" void kernel_launch(void* const* d_in, const int* in_sizes, int n_in,
                              void* d_out, int out_size)
{
    const float* x_user = (const float*)d_in[0];
    const float* x_item = (const float*)d_in[1];
    const int*   ei_ui  = (const int*)d_in[2];
    const int*   ei_iu  = (const int*)d_in[3];
    const float* q_w_user = (const float*)d_in[4];
    const float* q_b_user = (const float*)d_in[5];
    const float* k_w_user = (const float*)d_in[6];
    const float* k_b_user = (const float*)d_in[7];
    const float* v_w_user = (const float*)d_in[8];
    const float* v_b_user = (const float*)d_in[9];
    const float* q_w_item = (const float*)d_in[10];
    const float* q_b_item = (const float*)d_in[11];
    const float* k_w_item = (const float*)d_in[12];
    const float* k_b_item = (const float*)d_in[13];
    const float* v_w_item = (const float*)d_in[14];
    const float* v_b_item = (const float*)d_in[15];
    const float* W_ui = (const float*)d_in[16];
    const float* W_iu = (const float*)d_in[17];

    const int NU = in_sizes[0] / D;
    const int NI = in_sizes[1] / D;
    const int E_ui = in_sizes[2] / 2;
    const int E_iu = in_sizes[3] / 2;

    cudaFuncSetAttribute(gemm_batch, cudaFuncAttributeMaxDynamicSharedMemorySize, GEMM_SMEM);

    float *yu, *yi, *pA, *pcb, *pu, *pw, *pc0, *psum, *ps0, *ps1;
    __nv_bfloat16 *agg0, *agg1, *xbu, *xbi, *qv0, *qv1, *Wmb, *Vbb;
    int *deg0, *deg1, *cur0, *cur1, *off_ui, *off_iu, *src_ui_c, *src_iu_c;
    cudaGetSymbolAddress((void**)&yu, g_yu);
    cudaGetSymbolAddress((void**)&yi, g_yi);
    cudaGetSymbolAddress((void**)&agg0, g_agg);
    agg1 = agg0 + (size_t)MAXN * D;
    cudaGetSymbolAddress((void**)&xbu, g_xbu);
    cudaGetSymbolAddress((void**)&xbi, g_xbi);
    cudaGetSymbolAddress((void**)&qv0, g_qv);
    qv1 = qv0 + (size_t)MAXN * QVS;
    cudaGetSymbolAddress((void**)&pA, g_A);
    cudaGetSymbolAddress((void**)&pcb, g_cbv);
    cudaGetSymbolAddress((void**)&Wmb, g_Wmb);
    cudaGetSymbolAddress((void**)&Vbb, g_Vbb);
    cudaGetSymbolAddress((void**)&pu, g_u);
    cudaGetSymbolAddress((void**)&pw, g_w);
    cudaGetSymbolAddress((void**)&pc0, g_c0);
    cudaGetSymbolAddress((void**)&psum, g_sum);
    cudaGetSymbolAddress((void**)&ps0, g_s);
    ps1 = ps0 + MAXN;
    cudaGetSymbolAddress((void**)&deg0, g_deg);
    deg1 = deg0 + MAXN;
    cudaGetSymbolAddress((void**)&cur0, g_cur);
    cur1 = cur0 + MAXN;
    cudaGetSymbolAddress((void**)&off_ui, g_off_ui);
    cudaGetSymbolAddress((void**)&off_iu, g_off_iu);
    cudaGetSymbolAddress((void**)&src_ui_c, g_src_ui);
    cudaGetSymbolAddress((void**)&src_iu_c, g_src_iu);

    const int* src_ui = ei_ui;
    const int* dst_ui = ei_ui + E_ui;
    const int* src_iu = ei_iu;
    const int* dst_iu = ei_iu + E_iu;

    // per-pass weight pointers (p = layer*2 + edgetype; pass0 src=user dst=item, pass1 reversed)
    const float *QW[4], *QB[4], *WW[4], *KW[4], *KB[4], *VW[4];
    for (int l = 0; l < 2; ++l) {
        const size_t wo = (size_t)l * D * D;
        const size_t bo = (size_t)l * D;
        QW[2*l+0] = q_w_user + wo; QB[2*l+0] = q_b_user + bo; WW[2*l+0] = W_ui + wo;
        KW[2*l+0] = k_w_item + wo; KB[2*l+0] = k_b_item + bo; VW[2*l+0] = v_w_user + wo;
        QW[2*l+1] = q_w_item + wo; QB[2*l+1] = q_b_item + bo; WW[2*l+1] = W_iu + wo;
        KW[2*l+1] = k_w_user + wo; KB[2*l+1] = k_b_user + bo; VW[2*l+1] = v_w_item + wo;
    }

    // --- weight prep (2 chained stages, all 4 passes) ---
    {
        Prep1 p1;
        for (int p = 0; p < 4; ++p) { p1.qw[p] = QW[p]; p1.qb[p] = QB[p]; p1.W[p] = WW[p]; }
        p1.A = pA; p1.cb = pcb; p1.psum = psum;
        prep1_k<<<dim3(65, 4), 256>>>(p1);
        Prep2 p2;
        for (int p = 0; p < 4; ++p) { p2.kw[p] = KW[p]; p2.kb[p] = KB[p]; p2.vw[p] = VW[p]; }
        p2.A = pA; p2.cb = pcb; p2.Wmb = Wmb; p2.Vbb = Vbb; p2.u = pu; p2.w = pw; p2.c0 = pc0;
        prep2_k<<<dim3(129, 4), 256>>>(p2);
    }

    // --- CSR by dst for both edge types (built once, reused by both layers) ---
    cudaMemsetAsync(deg0, 0, 2 * (size_t)MAXN * sizeof(int));
    CountB cbt;
    cbt.dst[0] = dst_ui; cbt.deg[0] = deg0; cbt.E[0] = E_ui;
    cbt.dst[1] = dst_iu; cbt.deg[1] = deg1; cbt.E[1] = E_iu;
    count_b<<<dim3(512, 2), 256>>>(cbt);
    ScanB sbt;
    sbt.deg[0] = deg0; sbt.off[0] = off_ui; sbt.cur[0] = cur0; sbt.n[0] = NI;
    sbt.deg[1] = deg1; sbt.off[1] = off_iu; sbt.cur[1] = cur1; sbt.n[1] = NU;
    scan_b<<<2, 1024>>>(sbt);
    FillB fbt;
    fbt.dst[0] = dst_ui; fbt.src[0] = src_ui; fbt.cur[0] = cur0; fbt.csrc[0] = src_ui_c; fbt.E[0] = E_ui;
    fbt.dst[1] = dst_iu; fbt.src[1] = src_iu; fbt.cur[1] = cur1; fbt.csrc[1] = src_iu_c; fbt.E[1] = E_iu;
    fill_b<<<dim3(512, 2), 256>>>(fbt);

    const int maxN = (NU > NI) ? NU : NI;
    const int rows_grid = (maxN + 7) / 8;   // warp-per-row, 8 warps per block

    // --- layer-0 bf16 conversion + per-src scalars s (users->pass0 u[0], items->pass1 u[1]) ---
    {
        ConvB cv;
        cv.x[0] = x_user; cv.y[0] = xbu; cv.u[0] = pu + 0 * D; cv.c0[0] = pc0 + 0; cv.s[0] = ps0; cv.n[0] = NU;
        cv.x[1] = x_item; cv.y[1] = xbi; cv.u[1] = pu + 1 * D; cv.c0[1] = pc0 + 1; cv.s[1] = ps1; cv.n[1] = NI;
        conv_b16<<<dim3(rows_grid, 2), 256>>>(cv);
    }

    float* out_f = (float*)d_out;

    for (int l = 0; l < 2; ++l) {
        const float* in_u = (l == 0) ? x_user : yu;
        const float* in_i = (l == 0) ? x_item : yi;
        float* out_u = (l == 0) ? yu : out_f;
        float* out_i = (l == 0) ? yi : (out_f + (size_t)NU * D);

        const size_t bo = (size_t)l * D;
        const int p0 = 2 * l, p1 = 2 * l + 1;

        GemmBatch gb;
        // pass 0: a = x_user @ B^T + w ; v = x_user @ vw^T + vb   (both into qv0, stride QVS)
        gb.X[0] = xbu; gb.W[0] = Wmb + p0 * D * D; gb.bias[0] = pw + p0 * D;    gb.C[0] = qv0;       gb.N[0] = NU;
        gb.X[1] = xbu; gb.W[1] = Vbb + p0 * D * D; gb.bias[1] = v_b_user + bo; gb.C[1] = qv0 + 128; gb.N[1] = NU;
        // pass 1: from items
        gb.X[2] = xbi; gb.W[2] = Wmb + p1 * D * D; gb.bias[2] = pw + p1 * D;    gb.C[2] = qv1;       gb.N[2] = NI;
        gb.X[3] = xbi; gb.W[3] = Vbb + p1 * D * D; gb.bias[3] = v_b_item + bo; gb.C[3] = qv1 + 128; gb.N[3] = NI;
        gemm_batch<<<dim3((maxN + 127) / 128, 4), 256, GEMM_SMEM>>>(gb);

        EdgeBatch eb;
        eb.qv[0] = qv0; eb.xd[0] = xbi; eb.sarr[0] = ps0;
        eb.off[0] = off_ui; eb.csrc[0] = src_ui_c; eb.agg[0] = agg0; eb.n[0] = NI;
        eb.qv[1] = qv1; eb.xd[1] = xbu; eb.sarr[1] = ps1;
        eb.off[1] = off_iu; eb.csrc[1] = src_iu_c; eb.agg[1] = agg1; eb.n[1] = NU;
        eb.psum = psum + 2 * l;
        fused_edge_batch<<<dim3(1024, 2), 256>>>(eb);

        AxpyBatch ab;
        ab.xin[0] = in_u; ab.agg[0] = agg1; ab.gsum[0] = psum + p1; ab.out[0] = out_u;
        ab.xin[1] = in_i; ab.agg[1] = agg0; ab.gsum[1] = psum + p0; ab.out[1] = out_i;
        ab.n[0] = NU; ab.n[1] = NI;
        if (l == 0) {
            ab.outb[0] = xbu; ab.outb[1] = xbi;
            // next layer (l=1): users are src of pass p=2, items src of pass p=3
            ab.u[0] = pu + 2 * D; ab.c0[0] = pc0 + 2; ab.sout[0] = ps0;
            ab.u[1] = pu + 3 * D; ab.c0[1] = pc0 + 3; ab.sout[1] = ps1;
        } else {
            ab.outb[0] = nullptr; ab.outb[1] = nullptr;
            ab.u[0] = nullptr; ab.u[1] = nullptr;
            ab.c0[0] = nullptr; ab.c0[1] = nullptr;
            ab.sout[0] = nullptr; ab.sout[1] = nullptr;
        }
        axpy_batch<<<dim3(rows_grid, 2), 256>>>(ab);
    }
}